// round 15
// baseline (speedup 1.0000x reference)
#include <cuda_runtime.h>

#define N_NODES  100000
#define N_EDGES  1250000
#define N_GRAPHS 256
#define HID      64
#define IN_DIM   7

// ---------------- device scratch (no allocations allowed) ----------------
__device__ int   g_edge_cnt[N_NODES];
__device__ int   g_row_ptr[N_NODES + 1];
__device__ int   g_cursor[N_NODES];
__device__ float g_dinv[N_NODES];
__device__ int   g_csr_src[N_EDGES];
__device__ float g_csr_w[N_EDGES];
__device__ float g_xa[N_NODES * IN_DIM];
__device__ float g_bufA[N_NODES * HID];
__device__ float g_bufB[N_NODES * HID];
__device__ float g_pool[N_GRAPHS * HID];
__device__ float g_gcnt[N_GRAPHS];

// ---------------- preprocessing ----------------
__global__ void k_zero() {
    int i = blockIdx.x * blockDim.x + threadIdx.x;
    if (i < N_NODES) g_edge_cnt[i] = 0;
    if (i < N_GRAPHS * HID) g_pool[i] = 0.f;
    if (i < N_GRAPHS) g_gcnt[i] = 0.f;
}

__global__ void k_count(const int* __restrict__ dst) {
    int e = blockIdx.x * blockDim.x + threadIdx.x;
    if (e < N_EDGES) atomicAdd(&g_edge_cnt[dst[e]], 1);
}

// Single-block scan over 100001 counts -> row_ptr, cursor, dinv.
__global__ void k_scan() {
    __shared__ int sums[1024];
    const int CH = 98;                        // 1024*98 = 100352 >= 100001
    int t = threadIdx.x;
    int beg = t * CH;
    int s = 0;
    for (int i = beg; i < beg + CH; i++)
        if (i < N_NODES) s += g_edge_cnt[i];
    sums[t] = s;
    __syncthreads();
    for (int off = 1; off < 1024; off <<= 1) {
        int v = (t >= off) ? sums[t - off] : 0;
        __syncthreads();
        sums[t] += v;
        __syncthreads();
    }
    int run = sums[t] - s;                    // exclusive prefix of this chunk
    for (int i = beg; i < beg + CH; i++) {
        if (i <= N_NODES) {
            g_row_ptr[i] = run;
            if (i < N_NODES) {
                int c = g_edge_cnt[i];
                g_cursor[i] = run;
                g_dinv[i] = rsqrtf((float)(c + 1));   // +1 self-loop
                run += c;
            }
        }
    }
}

__global__ void k_fill(const int* __restrict__ src, const int* __restrict__ dst) {
    int e = blockIdx.x * blockDim.x + threadIdx.x;
    if (e >= N_EDGES) return;
    int s = src[e];
    int d = dst[e];
    int pos = atomicAdd(&g_cursor[d], 1);
    g_csr_src[pos] = s;
    g_csr_w[pos] = g_dinv[s] * g_dinv[d];
}

// ---------------- aggregation (warp per node) ----------------
// 7-dim aggregation of raw x (layer 1 uses Agg(X)*W1 == Agg(X*W1))
__global__ void k_agg7(const float* __restrict__ x) {
    int node = blockIdx.x * (blockDim.x >> 5) + (threadIdx.x >> 5);
    if (node >= N_NODES) return;
    int lane = threadIdx.x & 31;
    int rs = g_row_ptr[node], re = g_row_ptr[node + 1];
    float di = g_dinv[node];
    float acc = 0.f;
    if (lane < IN_DIM) acc = x[node * IN_DIM + lane] * di * di;  // self-loop
    for (int base = rs; base < re; base += 32) {
        int idx = base + lane;
        int s = 0; float w = 0.f;
        if (idx < re) { s = g_csr_src[idx]; w = g_csr_w[idx]; }
        int cnt = min(32, re - base);
        #pragma unroll 4
        for (int j = 0; j < cnt; j++) {
            int   sj = __shfl_sync(0xffffffffu, s, j);
            float wj = __shfl_sync(0xffffffffu, w, j);
            if (lane < IN_DIM) acc = fmaf(wj, x[sj * IN_DIM + lane], acc);
        }
    }
    if (lane < IN_DIM) g_xa[node * IN_DIM + lane] = acc;
}

// 64-dim aggregation: g_bufA[n] = sum_e w_e * g_bufB[src_e] + dinv^2*g_bufB[n]
//                                 + bias (optional relu)
__global__ void k_agg64(const float* __restrict__ bias, int do_relu) {
    int node = blockIdx.x * (blockDim.x >> 5) + (threadIdx.x >> 5);
    if (node >= N_NODES) return;
    int lane = threadIdx.x & 31;
    int rs = g_row_ptr[node], re = g_row_ptr[node + 1];
    float di = g_dinv[node];
    const float2* hp = (const float2*)g_bufB;
    float2 acc = hp[node * 32 + lane];        // self-loop term
    float ws = di * di;
    acc.x *= ws; acc.y *= ws;
    for (int base = rs; base < re; base += 32) {
        int idx = base + lane;
        int s = 0; float w = 0.f;
        if (idx < re) { s = g_csr_src[idx]; w = g_csr_w[idx]; }
        int cnt = min(32, re - base);
        #pragma unroll 4
        for (int j = 0; j < cnt; j++) {
            int   sj = __shfl_sync(0xffffffffu, s, j);
            float wj = __shfl_sync(0xffffffffu, w, j);
            float2 hv = hp[sj * 32 + lane];
            acc.x = fmaf(wj, hv.x, acc.x);
            acc.y = fmaf(wj, hv.y, acc.y);
        }
    }
    float2 b = ((const float2*)bias)[lane];
    acc.x += b.x; acc.y += b.y;
    if (do_relu) { acc.x = fmaxf(acc.x, 0.f); acc.y = fmaxf(acc.y, 0.f); }
    ((float2*)g_bufA)[node * 32 + lane] = acc;
}

// ---------------- dense GEMMs ----------------
// layer1: g_bufA = relu(g_xa[100000x7] @ W1[7x64] + b1)
__global__ void k_gemm7(const float* __restrict__ W1, const float* __restrict__ b1) {
    __shared__ float ws[IN_DIM][HID];
    __shared__ float bs[HID];
    int tid = threadIdx.x;                    // 256
    // FIX: 448 elements > 256 threads -> strided loader (was the 0.30 rel_err bug)
    for (int idx = tid; idx < IN_DIM * HID; idx += 256)
        ws[idx / HID][idx % HID] = W1[idx];
    if (tid < HID) bs[tid] = b1[tid];
    __syncthreads();
    int r = tid & 63, cg = tid >> 6;
    int gr = blockIdx.x * 64 + r;
    if (gr >= N_NODES) return;
    float xv[IN_DIM];
    #pragma unroll
    for (int k = 0; k < IN_DIM; k++) xv[k] = g_xa[gr * IN_DIM + k];
    float acc[16];
    #pragma unroll
    for (int c = 0; c < 16; c++) {
        float s = bs[cg * 16 + c];
        #pragma unroll
        for (int k = 0; k < IN_DIM; k++) s = fmaf(xv[k], ws[k][cg * 16 + c], s);
        acc[c] = fmaxf(s, 0.f);
    }
    float4* yp = (float4*)(g_bufA + gr * HID + cg * 16);
    #pragma unroll
    for (int q = 0; q < 4; q++)
        yp[q] = make_float4(acc[q*4], acc[q*4+1], acc[q*4+2], acc[q*4+3]);
}

// g_bufB[100000x64] = g_bufA[100000x64] @ W[64x64], no epilogue
__global__ void k_gemm64(const float* __restrict__ W) {
    __shared__ __align__(16) float xs[64][65];   // pad: kills 32-way conflict
    __shared__ __align__(16) float ws[64][64];
    int tid = threadIdx.x;                       // 256
    int r0 = blockIdx.x * 64;
    #pragma unroll
    for (int i = 0; i < 16; i++) {
        int idx = tid + i * 256;
        int row = idx >> 6, col = idx & 63;
        int gr = r0 + row;
        xs[row][col] = (gr < N_NODES) ? g_bufA[gr * 64 + col] : 0.f;
        ws[row][col] = W[idx];
    }
    __syncthreads();
    int r = tid & 63, cg = tid >> 6;
    float4 a0 = make_float4(0,0,0,0), a1 = a0, a2 = a0, a3 = a0;
    #pragma unroll
    for (int k = 0; k < 64; k++) {
        float xv = xs[r][k];
        const float4* wr = (const float4*)(&ws[k][0]) + cg * 4;  // broadcast
        float4 w0 = wr[0], w1 = wr[1], w2 = wr[2], w3 = wr[3];
        a0.x = fmaf(xv, w0.x, a0.x); a0.y = fmaf(xv, w0.y, a0.y);
        a0.z = fmaf(xv, w0.z, a0.z); a0.w = fmaf(xv, w0.w, a0.w);
        a1.x = fmaf(xv, w1.x, a1.x); a1.y = fmaf(xv, w1.y, a1.y);
        a1.z = fmaf(xv, w1.z, a1.z); a1.w = fmaf(xv, w1.w, a1.w);
        a2.x = fmaf(xv, w2.x, a2.x); a2.y = fmaf(xv, w2.y, a2.y);
        a2.z = fmaf(xv, w2.z, a2.z); a2.w = fmaf(xv, w2.w, a2.w);
        a3.x = fmaf(xv, w3.x, a3.x); a3.y = fmaf(xv, w3.y, a3.y);
        a3.z = fmaf(xv, w3.z, a3.z); a3.w = fmaf(xv, w3.w, a3.w);
    }
    int gr = r0 + r;
    if (gr < N_NODES) {
        float4* yp = (float4*)(g_bufB + gr * 64 + cg * 16);
        yp[0] = a0; yp[1] = a1; yp[2] = a2; yp[3] = a3;
    }
}

// ---------------- pooling + head ----------------
// batch is sorted: warp handles 32 consecutive nodes, register-accumulate,
// flush atomics only at segment boundaries. Reads g_bufA.
__global__ void k_pool(const int* __restrict__ batch) {
    const int CHUNK = 32;
    int warp = blockIdx.x * (blockDim.x >> 5) + (threadIdx.x >> 5);
    int lane = threadIdx.x & 31;
    int n0 = warp * CHUNK;
    if (n0 >= N_NODES) return;
    int n1 = min(n0 + CHUNK, N_NODES);
    const float2* hp = (const float2*)g_bufA;
    float2 acc = make_float2(0.f, 0.f);
    int curg = batch[n0];
    float c = 0.f;
    for (int n = n0; n < n1; n++) {
        int g = batch[n];
        if (g != curg) {
            atomicAdd(&g_pool[curg * HID + lane * 2],     acc.x);
            atomicAdd(&g_pool[curg * HID + lane * 2 + 1], acc.y);
            if (lane == 0) atomicAdd(&g_gcnt[curg], c);
            acc = make_float2(0.f, 0.f); c = 0.f; curg = g;
        }
        float2 hv = hp[n * 32 + lane];
        acc.x += hv.x; acc.y += hv.y;
        c += 1.f;
    }
    atomicAdd(&g_pool[curg * HID + lane * 2],     acc.x);
    atomicAdd(&g_pool[curg * HID + lane * 2 + 1], acc.y);
    if (lane == 0) atomicAdd(&g_gcnt[curg], c);
}

__global__ void k_final(const float* __restrict__ Wl, const float* __restrict__ bl,
                        float* __restrict__ out) {
    int t = threadIdx.x;
    if (t >= N_GRAPHS * 2) return;
    int g = t >> 1, o = t & 1;
    float inv = 1.f / fmaxf(g_gcnt[g], 1.f);
    float s = 0.f;
    #pragma unroll
    for (int k = 0; k < HID; k++)
        s = fmaf(g_pool[g * HID + k], Wl[k * 2 + o], s);
    out[t] = s * inv + bl[o];
}

// ---------------- launch (kernel launches ONLY — graph-capturable) ----------
extern "C" void kernel_launch(void* const* d_in, const int* in_sizes, int n_in,
                              void* d_out, int out_size) {
    const float* x     = (const float*)d_in[0];
    const int*   ei    = (const int*)d_in[1];    // int32 (JAX x64 disabled)
    const int*   batch = (const int*)d_in[2];    // int32
    const float* W1 = (const float*)d_in[3];
    const float* b1 = (const float*)d_in[4];
    const float* W2 = (const float*)d_in[5];
    const float* b2 = (const float*)d_in[6];
    const float* W3 = (const float*)d_in[7];
    const float* b3 = (const float*)d_in[8];
    const float* Wl = (const float*)d_in[9];
    const float* bl = (const float*)d_in[10];
    float* out = (float*)d_out;

    const int TB = 256;
    int eb = (N_EDGES + TB - 1) / TB;
    int nb = (N_NODES + TB - 1) / TB;
    int ab = (N_NODES + 7) / 8;           // warp per node, 8 warps/block
    int gb = (N_NODES + 63) / 64;         // 64 rows per GEMM block
    int pb = ((N_NODES + 31) / 32 + 7) / 8;

    k_zero  <<<nb, TB>>>();
    k_count <<<eb, TB>>>(ei + N_EDGES);           // dst row
    k_scan  <<<1, 1024>>>();
    k_fill  <<<eb, TB>>>(ei, ei + N_EDGES);       // src row, dst row

    // layer 1: Agg(x) in 7-dim, then 7->64 GEMM (+b1, relu) -> bufA
    k_agg7  <<<ab, TB>>>(x);
    k_gemm7 <<<gb, TB>>>(W1, b1);

    // layer 2: GEMM 64->64 (bufA->bufB), Agg (+b2, relu) (bufB->bufA)
    k_gemm64<<<gb, TB>>>(W2);
    k_agg64 <<<ab, TB>>>(b2, 1);

    // layer 3: GEMM 64->64 (bufA->bufB), Agg (+b3) (bufB->bufA)
    k_gemm64<<<gb, TB>>>(W3);
    k_agg64 <<<ab, TB>>>(b3, 0);

    // mean pool + head
    k_pool  <<<pb, TB>>>(batch);
    k_final <<<1, 512>>>(Wl, bl, out);
}